// round 2
// baseline (speedup 1.0000x reference)
#include <cuda_runtime.h>
#include <math.h>

#define UNITS 1024
#define NB    32
#define NT    2048
#define M_TOTAL (NB * NT)

#define BM 64
#define BN 64
#define BK 16

// Scratch (allocation-free rule: __device__ globals)
__device__ float g_c[NB * UNITS];      // c[b][v] = W1_b[v] + W2_b[v] + hidden[b]·W2_w[v,:]
__device__ float g_score[NB * NT];     // pre-softmax scores

// ---------------------------------------------------------------------------
// Kernel A: per-batch bias vector c[b][v]
// ---------------------------------------------------------------------------
__global__ void bias_hidden_kernel(const float* __restrict__ hidden,
                                   const float* __restrict__ W2_w,
                                   const float* __restrict__ W1_b,
                                   const float* __restrict__ W2_b) {
    __shared__ float hs[UNITS];
    const int b = blockIdx.x;
    for (int u = threadIdx.x; u < UNITS; u += blockDim.x)
        hs[u] = hidden[b * UNITS + u];
    __syncthreads();

    const int warp  = threadIdx.x >> 5;
    const int lane  = threadIdx.x & 31;
    const int nwarp = blockDim.x >> 5;
    for (int v = warp; v < UNITS; v += nwarp) {
        const float* wrow = W2_w + (size_t)v * UNITS;
        float s = 0.f;
        #pragma unroll 4
        for (int u = lane; u < UNITS; u += 32)
            s += hs[u] * wrow[u];
        #pragma unroll
        for (int m = 16; m; m >>= 1)
            s += __shfl_xor_sync(0xffffffffu, s, m);
        if (lane == 0)
            g_c[b * UNITS + v] = s + W1_b[v] + W2_b[v];
    }
}

// ---------------------------------------------------------------------------
// Kernel B: fused  score[m] = sum_n V[n] * tanh( x[m,:]·W1[n,:] + c[b][n] )
// Tiled 64x64x16 fp32 GEMM, 256 threads, 4x4 register blocking,
// tanh+V reduction in the epilogue (att never materialized).
// ---------------------------------------------------------------------------
__global__ __launch_bounds__(256) void score_kernel(
    const float* __restrict__ x,
    const float* __restrict__ W1_w,
    const float* __restrict__ V_w) {
    __shared__ float As[BK][BM];   // x tile, transposed: As[k][m]
    __shared__ float Bs[BK][BN];   // W1 tile, transposed: Bs[k][n]
    __shared__ float cs[UNITS];
    __shared__ float vs[UNITS];

    const int tid = threadIdx.x;
    const int m0  = blockIdx.x * BM;
    const int b   = m0 / NT;            // 2048 % 64 == 0 -> whole tile same batch

    for (int i = tid; i < UNITS; i += 256) {
        cs[i] = g_c[b * UNITS + i];
        vs[i] = V_w[i];
    }

    const int tx = tid & 15;            // n sub-tile
    const int ty = tid >> 4;            // m sub-tile
    const int lr = tid >> 2;            // load row 0..63
    const int lq = tid & 3;             // float4 index within 16-wide k slab

    float score_acc[4] = {0.f, 0.f, 0.f, 0.f};

    const float* xbase = x + (size_t)(m0 + lr) * UNITS + lq * 4;
    __syncthreads();

    for (int n0 = 0; n0 < UNITS; n0 += BN) {
        float acc[4][4];
        #pragma unroll
        for (int i = 0; i < 4; i++)
            #pragma unroll
            for (int j = 0; j < 4; j++) acc[i][j] = 0.f;

        const float* wbase = W1_w + (size_t)(n0 + lr) * UNITS + lq * 4;

        for (int kk = 0; kk < UNITS; kk += BK) {
            const float4 av = *(const float4*)(xbase + kk);
            const float4 bv = *(const float4*)(wbase + kk);
            __syncthreads();   // previous tile's compute done
            As[lq * 4 + 0][lr] = av.x;
            As[lq * 4 + 1][lr] = av.y;
            As[lq * 4 + 2][lr] = av.z;
            As[lq * 4 + 3][lr] = av.w;
            Bs[lq * 4 + 0][lr] = bv.x;
            Bs[lq * 4 + 1][lr] = bv.y;
            Bs[lq * 4 + 2][lr] = bv.z;
            Bs[lq * 4 + 3][lr] = bv.w;
            __syncthreads();

            #pragma unroll
            for (int k = 0; k < BK; k++) {
                const float4 a  = *(const float4*)&As[k][ty * 4];
                const float4 bb = *(const float4*)&Bs[k][tx * 4];
                acc[0][0] += a.x * bb.x; acc[0][1] += a.x * bb.y;
                acc[0][2] += a.x * bb.z; acc[0][3] += a.x * bb.w;
                acc[1][0] += a.y * bb.x; acc[1][1] += a.y * bb.y;
                acc[1][2] += a.y * bb.z; acc[1][3] += a.y * bb.w;
                acc[2][0] += a.z * bb.x; acc[2][1] += a.z * bb.y;
                acc[2][2] += a.z * bb.z; acc[2][3] += a.z * bb.w;
                acc[3][0] += a.w * bb.x; acc[3][1] += a.w * bb.y;
                acc[3][2] += a.w * bb.z; acc[3][3] += a.w * bb.w;
            }
        }

        // Epilogue: tanh + V-weighted reduction (no att materialization)
        #pragma unroll
        for (int i = 0; i < 4; i++) {
            #pragma unroll
            for (int j = 0; j < 4; j++) {
                const int n = n0 + tx * 4 + j;
                score_acc[i] += tanhf(acc[i][j] + cs[n]) * vs[n];
            }
        }
    }

    // Reduce across the 16 tx lanes (same 16-lane half-warp per ty)
    #pragma unroll
    for (int i = 0; i < 4; i++) {
        float v = score_acc[i];
        #pragma unroll
        for (int m = 8; m; m >>= 1)
            v += __shfl_xor_sync(0xffffffffu, v, m);
        if (tx == 0)
            g_score[m0 + ty * 4 + i] = v;
    }
}

// ---------------------------------------------------------------------------
// Kernel C: softmax over T per batch -> attention weights (written to d_out)
// ---------------------------------------------------------------------------
__global__ void softmax_kernel(float* __restrict__ out_w) {
    __shared__ float s[NT];
    __shared__ float red[32];
    const int b   = blockIdx.x;
    const int tid = threadIdx.x;   // 256
    const int lane = tid & 31, warp = tid >> 5;

    float lmax = -INFINITY;
    for (int t = tid; t < NT; t += 256) {
        const float v = g_score[b * NT + t];
        s[t] = v;
        lmax = fmaxf(lmax, v);
    }
    #pragma unroll
    for (int m = 16; m; m >>= 1)
        lmax = fmaxf(lmax, __shfl_xor_sync(0xffffffffu, lmax, m));
    if (lane == 0) red[warp] = lmax;
    __syncthreads();
    float bmax = red[0];
    #pragma unroll
    for (int w = 1; w < 8; w++) bmax = fmaxf(bmax, red[w]);

    float lsum = 0.f;
    for (int t = tid; t < NT; t += 256) {
        const float e = __expf(s[t] - bmax);
        s[t] = e;
        lsum += e;
    }
    #pragma unroll
    for (int m = 16; m; m >>= 1)
        lsum += __shfl_xor_sync(0xffffffffu, lsum, m);
    __syncthreads();
    if (lane == 0) red[warp] = lsum;
    __syncthreads();
    float bsum = 0.f;
    #pragma unroll
    for (int w = 0; w < 8; w++) bsum += red[w];
    const float inv = 1.f / bsum;

    for (int t = tid; t < NT; t += 256)
        out_w[b * NT + t] = s[t] * inv;
}

// ---------------------------------------------------------------------------
// Kernel D: context[b,u] = sum_t w[b,t] * x[b,t,u]
// ---------------------------------------------------------------------------
__global__ __launch_bounds__(256) void context_kernel(
    const float* __restrict__ x,
    const float* __restrict__ w,
    float* __restrict__ out_ctx) {
    __shared__ float ws[NT];
    const int b = blockIdx.x;
    const int u = blockIdx.y * 256 + threadIdx.x;
    for (int t = threadIdx.x; t < NT; t += 256)
        ws[t] = w[b * NT + t];
    __syncthreads();

    float a0 = 0.f, a1 = 0.f, a2 = 0.f, a3 = 0.f;
    const float* xp = x + (size_t)b * NT * UNITS + u;
    for (int t = 0; t < NT; t += 4) {
        a0 += ws[t + 0] * xp[(size_t)(t + 0) * UNITS];
        a1 += ws[t + 1] * xp[(size_t)(t + 1) * UNITS];
        a2 += ws[t + 2] * xp[(size_t)(t + 2) * UNITS];
        a3 += ws[t + 3] * xp[(size_t)(t + 3) * UNITS];
    }
    out_ctx[b * UNITS + u] = (a0 + a1) + (a2 + a3);
}

// ---------------------------------------------------------------------------
extern "C" void kernel_launch(void* const* d_in, const int* in_sizes, int n_in,
                              void* d_out, int out_size) {
    const float* x      = (const float*)d_in[0];
    const float* hidden = (const float*)d_in[1];
    const float* W1_w   = (const float*)d_in[2];
    const float* W1_b   = (const float*)d_in[3];
    const float* W2_w   = (const float*)d_in[4];
    const float* W2_b   = (const float*)d_in[5];
    const float* V_w    = (const float*)d_in[6];
    // d_in[7] = V_b: constant score offset -> softmax-invariant -> unused.

    float* out     = (float*)d_out;
    float* out_ctx = out;                   // context: 32*1024 floats
    float* out_w   = out + NB * UNITS;      // weights: 32*2048 floats

    bias_hidden_kernel<<<NB, 256>>>(hidden, W2_w, W1_b, W2_b);
    score_kernel<<<M_TOTAL / BM, 256>>>(x, W1_w, V_w);
    softmax_kernel<<<NB, 256>>>(out_w);
    context_kernel<<<dim3(NB, 4), 256>>>(x, out_w, out_ctx);
}

// round 4
// speedup vs baseline: 3.4894x; 3.4894x over previous
#include <cuda_runtime.h>
#include <math.h>
#include <stdint.h>

#define UNITS 1024
#define NB    32
#define NT    2048
#define M_TOTAL (NB * NT)

#define M_TILE 128
#define N_CHUNK 128
#define BK 32
#define N_CHUNKS (UNITS / N_CHUNK)   // 8
#define K_TILES  (UNITS / BK)        // 32

// ---- scratch (allocation-free rule) ----
__device__ float g_c[NB * UNITS];
__device__ float g_score[NB * NT];
#define CTX_SPLIT 8
__device__ float g_ctxp[CTX_SPLIT * NB * UNITS];

__device__ __forceinline__ float to_tf32(float f) {
    uint32_t u;
    asm("cvt.rna.tf32.f32 %0, %1;" : "=r"(u) : "f"(f));
    return __uint_as_float(u);
}

__device__ __forceinline__ void mma_tf32(float d[4], const uint32_t a[4],
                                         const uint32_t b[2]) {
    asm volatile(
        "mma.sync.aligned.m16n8k8.row.col.f32.tf32.tf32.f32 "
        "{%0,%1,%2,%3}, {%4,%5,%6,%7}, {%8,%9}, {%0,%1,%2,%3};"
        : "+f"(d[0]), "+f"(d[1]), "+f"(d[2]), "+f"(d[3])
        : "r"(a[0]), "r"(a[1]), "r"(a[2]), "r"(a[3]), "r"(b[0]), "r"(b[1]));
}

// ============================ Kernel A: c[b][v] ============================
__global__ void bias_hidden_kernel(const float* __restrict__ hidden,
                                   const float* __restrict__ W2_w,
                                   const float* __restrict__ W1_b,
                                   const float* __restrict__ W2_b) {
    __shared__ float hs[UNITS];
    const int b = blockIdx.x;
    for (int u = threadIdx.x; u < UNITS; u += 256)
        hs[u] = hidden[b * UNITS + u];
    __syncthreads();
    const int warp = threadIdx.x >> 5, lane = threadIdx.x & 31;
    const int v0 = blockIdx.y * 128;
    for (int v = v0 + warp; v < v0 + 128; v += 8) {
        const float* wr = W2_w + (size_t)v * UNITS;
        float s = 0.f;
        #pragma unroll 8
        for (int u = lane; u < UNITS; u += 32) s += hs[u] * wr[u];
        #pragma unroll
        for (int m = 16; m; m >>= 1) s += __shfl_xor_sync(0xffffffffu, s, m);
        if (lane == 0) g_c[b * UNITS + v] = s + W1_b[v] + W2_b[v];
    }
}

// ========== Kernel B: tf32 mma.sync GEMM + fused tanh/V epilogue ==========
// CTA: 128 rows x full K; 8 N-chunks of 128. 8 warps = 4(m) x 2(n).
// Warp tile 32x64: 2 m16 frags x 8 n8 frags, m16n8k8.
__global__ void __launch_bounds__(256, 1) score_kernel(
    const float* __restrict__ x,
    const float* __restrict__ W1,
    const float* __restrict__ Vw) {
    __shared__ float A_s[M_TILE][BK + 4];   // [m][k]  (+4 pad: conflict-free)
    __shared__ float B_s[N_CHUNK][BK + 4];  // [n][k]
    __shared__ float cs[UNITS];
    __shared__ float vs[UNITS];
    __shared__ float sred[2][M_TILE];

    const int tid  = threadIdx.x;
    const int wid  = tid >> 5, lane = tid & 31;
    const int wm   = wid >> 1;          // 0..3  -> rows wm*32
    const int wn   = wid & 1;           // 0..1  -> cols wn*64
    const int grp  = lane >> 2;         // 0..7
    const int thr  = lane & 3;          // 0..3
    const int m0   = blockIdx.x * M_TILE;
    const int b    = m0 / NT;

    for (int i = tid; i < UNITS; i += 256) {
        cs[i] = g_c[b * UNITS + i];
        vs[i] = Vw[i];
    }

    // global-load mapping: 8 float4 per 32-float row slab
    const int arow = tid >> 3;          // with j*32 offset below
    const int aq   = tid & 7;

    float sacc[2][2] = {{0.f, 0.f}, {0.f, 0.f}};   // [mf][half]

    for (int nc = 0; nc < N_CHUNKS; ++nc) {
        const int n0 = nc * N_CHUNK;
        float d[2][8][4];
        #pragma unroll
        for (int mf = 0; mf < 2; ++mf)
            #pragma unroll
            for (int nf = 0; nf < 8; ++nf)
                #pragma unroll
                for (int q = 0; q < 4; ++q) d[mf][nf][q] = 0.f;

        // prefetch k-tile 0
        float4 pa[4], pb[4];
        #pragma unroll
        for (int j = 0; j < 4; ++j) {
            pa[j] = *(const float4*)(x  + (size_t)(m0 + arow + j * 32) * UNITS + aq * 4);
            pb[j] = *(const float4*)(W1 + (size_t)(n0 + arow + j * 32) * UNITS + aq * 4);
        }

        for (int kt = 0; kt < K_TILES; ++kt) {
            __syncthreads();   // previous tile's compute done
            #pragma unroll
            for (int j = 0; j < 4; ++j) {
                float4 va = pa[j], vb = pb[j];
                va.x = to_tf32(va.x); va.y = to_tf32(va.y);
                va.z = to_tf32(va.z); va.w = to_tf32(va.w);
                vb.x = to_tf32(vb.x); vb.y = to_tf32(vb.y);
                vb.z = to_tf32(vb.z); vb.w = to_tf32(vb.w);
                *(float4*)&A_s[arow + j * 32][aq * 4] = va;
                *(float4*)&B_s[arow + j * 32][aq * 4] = vb;
            }
            __syncthreads();

            if (kt + 1 < K_TILES) {
                const int k0 = (kt + 1) * BK;
                #pragma unroll
                for (int j = 0; j < 4; ++j) {
                    pa[j] = *(const float4*)(x  + (size_t)(m0 + arow + j * 32) * UNITS + k0 + aq * 4);
                    pb[j] = *(const float4*)(W1 + (size_t)(n0 + arow + j * 32) * UNITS + k0 + aq * 4);
                }
            }

            #pragma unroll
            for (int ks = 0; ks < 4; ++ks) {
                const int k = ks * 8 + thr;
                uint32_t af[2][4];
                #pragma unroll
                for (int mf = 0; mf < 2; ++mf) {
                    const int r = wm * 32 + mf * 16 + grp;
                    af[mf][0] = __float_as_uint(A_s[r][k]);
                    af[mf][1] = __float_as_uint(A_s[r + 8][k]);
                    af[mf][2] = __float_as_uint(A_s[r][k + 4]);
                    af[mf][3] = __float_as_uint(A_s[r + 8][k + 4]);
                }
                #pragma unroll
                for (int nf = 0; nf < 8; ++nf) {
                    const int n = wn * 64 + nf * 8 + grp;
                    uint32_t bf[2];
                    bf[0] = __float_as_uint(B_s[n][k]);
                    bf[1] = __float_as_uint(B_s[n][k + 4]);
                    mma_tf32(d[0][nf], af[0], bf);
                    mma_tf32(d[1][nf], af[1], bf);
                }
            }
        }

        // Epilogue: tanh + V-weighted reduce into per-row partials
        #pragma unroll
        for (int mf = 0; mf < 2; ++mf) {
            #pragma unroll
            for (int nf = 0; nf < 8; ++nf) {
                const int n = n0 + wn * 64 + nf * 8 + 2 * thr;
                sacc[mf][0] += tanhf(d[mf][nf][0] + cs[n])     * vs[n];
                sacc[mf][0] += tanhf(d[mf][nf][1] + cs[n + 1]) * vs[n + 1];
                sacc[mf][1] += tanhf(d[mf][nf][2] + cs[n])     * vs[n];
                sacc[mf][1] += tanhf(d[mf][nf][3] + cs[n + 1]) * vs[n + 1];
            }
        }
    }

    // Reduce within quad (lanes sharing a row), then across the 2 wn warps
    #pragma unroll
    for (int mf = 0; mf < 2; ++mf) {
        #pragma unroll
        for (int h = 0; h < 2; ++h) {
            float v = sacc[mf][h];
            v += __shfl_xor_sync(0xffffffffu, v, 1);
            v += __shfl_xor_sync(0xffffffffu, v, 2);
            if (thr == 0)
                sred[wn][wm * 32 + mf * 16 + h * 8 + grp] = v;
        }
    }
    __syncthreads();
    if (tid < M_TILE)
        g_score[m0 + tid] = sred[0][tid] + sred[1][tid];
}

// ======================= Kernel C: softmax per batch =======================
__global__ void softmax_kernel(float* __restrict__ out_w) {
    __shared__ float s[NT];
    __shared__ float red[32];
    const int b = blockIdx.x;
    const int tid = threadIdx.x;
    const int lane = tid & 31, warp = tid >> 5;

    float lmax = -INFINITY;
    for (int t = tid; t < NT; t += 256) {
        const float v = g_score[b * NT + t];
        s[t] = v;
        lmax = fmaxf(lmax, v);
    }
    #pragma unroll
    for (int m = 16; m; m >>= 1)
        lmax = fmaxf(lmax, __shfl_xor_sync(0xffffffffu, lmax, m));
    if (lane == 0) red[warp] = lmax;
    __syncthreads();
    float bmax = red[0];
    #pragma unroll
    for (int w = 1; w < 8; w++) bmax = fmaxf(bmax, red[w]);

    float lsum = 0.f;
    for (int t = tid; t < NT; t += 256) {
        const float e = __expf(s[t] - bmax);
        s[t] = e;
        lsum += e;
    }
    #pragma unroll
    for (int m = 16; m; m >>= 1)
        lsum += __shfl_xor_sync(0xffffffffu, lsum, m);
    __syncthreads();
    if (lane == 0) red[warp] = lsum;
    __syncthreads();
    float bsum = 0.f;
    #pragma unroll
    for (int w = 0; w < 8; w++) bsum += red[w];
    const float inv = 1.f / bsum;
    for (int t = tid; t < NT; t += 256)
        out_w[b * NT + t] = s[t] * inv;
}

// ================= Kernel D: context partials (8-way t-split) ==============
__global__ void __launch_bounds__(256) context_part_kernel(
    const float* __restrict__ x, const float* __restrict__ w) {
    __shared__ float ws[NT / CTX_SPLIT];    // 256
    const int b  = blockIdx.x;
    const int uc = blockIdx.y;
    const int tc = blockIdx.z;
    const int t0 = tc * (NT / CTX_SPLIT);
    ws[threadIdx.x] = w[b * NT + t0 + threadIdx.x];
    __syncthreads();
    const int u = uc * 256 + threadIdx.x;
    const float* xp = x + (size_t)b * NT * UNITS + (size_t)t0 * UNITS + u;
    float a0 = 0.f, a1 = 0.f, a2 = 0.f, a3 = 0.f;
    for (int t = 0; t < NT / CTX_SPLIT; t += 4) {
        a0 += ws[t + 0] * xp[(size_t)(t + 0) * UNITS];
        a1 += ws[t + 1] * xp[(size_t)(t + 1) * UNITS];
        a2 += ws[t + 2] * xp[(size_t)(t + 2) * UNITS];
        a3 += ws[t + 3] * xp[(size_t)(t + 3) * UNITS];
    }
    g_ctxp[(size_t)tc * NB * UNITS + b * UNITS + u] = (a0 + a1) + (a2 + a3);
}

__global__ void context_reduce_kernel(float* __restrict__ out_ctx) {
    const int i = blockIdx.x * 256 + threadIdx.x;   // 0..32767
    float s = 0.f;
    #pragma unroll
    for (int p = 0; p < CTX_SPLIT; ++p)
        s += g_ctxp[(size_t)p * NB * UNITS + i];
    out_ctx[i] = s;
}

// ---------------------------------------------------------------------------
extern "C" void kernel_launch(void* const* d_in, const int* in_sizes, int n_in,
                              void* d_out, int out_size) {
    const float* x      = (const float*)d_in[0];
    const float* hidden = (const float*)d_in[1];
    const float* W1_w   = (const float*)d_in[2];
    const float* W1_b   = (const float*)d_in[3];
    const float* W2_w   = (const float*)d_in[4];
    const float* W2_b   = (const float*)d_in[5];
    const float* V_w    = (const float*)d_in[6];
    // d_in[7] = V_b: softmax-invariant, unused.

    float* out     = (float*)d_out;
    float* out_ctx = out;                   // 32*1024
    float* out_w   = out + NB * UNITS;      // 32*2048

    bias_hidden_kernel<<<dim3(NB, 8), 256>>>(hidden, W2_w, W1_b, W2_b);
    score_kernel<<<M_TOTAL / M_TILE, 256>>>(x, W1_w, V_w);
    softmax_kernel<<<NB, 256>>>(out_w);
    context_part_kernel<<<dim3(NB, 4, CTX_SPLIT), 256>>>(x, out_w);
    context_reduce_kernel<<<NB * UNITS / 256, 256>>>(out_ctx);
}

// round 5
// speedup vs baseline: 4.9495x; 1.4184x over previous
#include <cuda_runtime.h>
#include <cuda_fp16.h>
#include <math.h>
#include <stdint.h>

#define UNITS 1024
#define NB    32
#define NT    2048
#define M_TOTAL (NB * NT)

#define M_TILE 128
#define N_CHUNK 128
#define BK 32
#define N_CHUNKS (UNITS / N_CHUNK)   // 8
#define K_TILES  (UNITS / BK)        // 32
#define PAD 8                         // halves; row stride 40 halves = 80B

// ---- scratch (allocation-free rule) ----
__device__ float g_c[NB * UNITS];
__device__ float g_score[NB * NT];
#define CTX_SPLIT 8
__device__ float g_ctxp[CTX_SPLIT * NB * UNITS];

__device__ __forceinline__ uint32_t sptr(const void* p) {
    return (uint32_t)__cvta_generic_to_shared(p);
}
__device__ __forceinline__ uint2 f4_to_h4(float4 v) {
    __half2 lo = __floats2half2_rn(v.x, v.y);
    __half2 hi = __floats2half2_rn(v.z, v.w);
    uint2 r;
    r.x = *(uint32_t*)&lo;
    r.y = *(uint32_t*)&hi;
    return r;
}
#define LDMX4(r0, r1, r2, r3, a) \
    asm volatile("ldmatrix.sync.aligned.m8n8.x4.shared.b16 {%0,%1,%2,%3}, [%4];" \
                 : "=r"(r0), "=r"(r1), "=r"(r2), "=r"(r3) : "r"(a))

__device__ __forceinline__ void mma_f16(float d[4], const uint32_t a[4],
                                        const uint32_t b0, const uint32_t b1) {
    asm volatile(
        "mma.sync.aligned.m16n8k16.row.col.f32.f16.f16.f32 "
        "{%0,%1,%2,%3}, {%4,%5,%6,%7}, {%8,%9}, {%0,%1,%2,%3};"
        : "+f"(d[0]), "+f"(d[1]), "+f"(d[2]), "+f"(d[3])
        : "r"(a[0]), "r"(a[1]), "r"(a[2]), "r"(a[3]), "r"(b0), "r"(b1));
}

// ============================ Kernel A: c[b][v] ============================
__global__ void bias_hidden_kernel(const float* __restrict__ hidden,
                                   const float* __restrict__ W2_w,
                                   const float* __restrict__ W1_b,
                                   const float* __restrict__ W2_b) {
    __shared__ float hs[UNITS];
    const int b = blockIdx.x;
    for (int u = threadIdx.x; u < UNITS; u += 256)
        hs[u] = hidden[b * UNITS + u];
    __syncthreads();
    const int warp = threadIdx.x >> 5, lane = threadIdx.x & 31;
    const int v0 = blockIdx.y * 128;
    for (int v = v0 + warp; v < v0 + 128; v += 8) {
        const float* wr = W2_w + (size_t)v * UNITS;
        float s = 0.f;
        #pragma unroll 8
        for (int u = lane; u < UNITS; u += 32) s += hs[u] * wr[u];
        #pragma unroll
        for (int m = 16; m; m >>= 1) s += __shfl_xor_sync(0xffffffffu, s, m);
        if (lane == 0) g_c[b * UNITS + v] = s + W1_b[v] + W2_b[v];
    }
}

// ====== Kernel B: fp16 mma.sync m16n8k16 + ldmatrix + fused tanh/V =========
// CTA: 128 rows x full K; 8 N-chunks of 128. 8 warps = 4(m) x 2(n).
// Warp tile 32x64: 2 m16 frags x 8 n8 frags.
__global__ void __launch_bounds__(256, 1) score_kernel(
    const float* __restrict__ x,
    const float* __restrict__ W1,
    const float* __restrict__ Vw) {
    __shared__ __half A_h[M_TILE][BK + PAD];
    __shared__ __half B_h[N_CHUNK][BK + PAD];
    __shared__ float cs[UNITS];
    __shared__ float vs[UNITS];
    __shared__ float sred[2][M_TILE];

    const int tid  = threadIdx.x;
    const int wid  = tid >> 5, lane = tid & 31;
    const int wm   = wid >> 1;          // 0..3  -> rows wm*32
    const int wn   = wid & 1;           // 0..1  -> cols wn*64
    const int grp  = lane >> 2;         // 0..7
    const int thr  = lane & 3;          // 0..3
    const int m0   = blockIdx.x * M_TILE;
    const int b    = m0 / NT;

    for (int i = tid; i < UNITS; i += 256) {
        cs[i] = g_c[b * UNITS + i];
        vs[i] = Vw[i];
    }

    // global-load mapping: 4 float4 per thread per tile (A and B each)
    const int grow = tid >> 3;          // 0..31, +j*32
    const int gseg = tid & 7;           // float4 segment within 32-col row

    // ldmatrix base addresses (per-lane, byte offsets added in-loop)
    // A: rows wm*32 + (lane&15), col (lane>>4)*8 halves
    const uint32_t a_base = sptr(&A_h[wm * 32 + (lane & 15)][(lane >> 4) * 8]);
    // B: rows wn*64 + (lane>>4)*8 + (lane&7), col ((lane>>3)&1)*8 halves
    const uint32_t b_base =
        sptr(&B_h[wn * 64 + ((lane >> 4) << 3) + (lane & 7)][((lane >> 3) & 1) * 8]);
    const uint32_t ROWB = (BK + PAD) * 2;      // 80 bytes per row

    float sacc[2][2] = {{0.f, 0.f}, {0.f, 0.f}};   // [mf][half]

    for (int nc = 0; nc < N_CHUNKS; ++nc) {
        const int n0 = nc * N_CHUNK;
        float d[2][8][4];
        #pragma unroll
        for (int mf = 0; mf < 2; ++mf)
            #pragma unroll
            for (int nf = 0; nf < 8; ++nf)
                #pragma unroll
                for (int q = 0; q < 4; ++q) d[mf][nf][q] = 0.f;

        // prefetch k-tile 0
        float4 pa[4], pb[4];
        #pragma unroll
        for (int j = 0; j < 4; ++j) {
            pa[j] = *(const float4*)(x  + (size_t)(m0 + grow + j * 32) * UNITS + gseg * 4);
            pb[j] = *(const float4*)(W1 + (size_t)(n0 + grow + j * 32) * UNITS + gseg * 4);
        }

        for (int kt = 0; kt < K_TILES; ++kt) {
            __syncthreads();   // previous tile's compute done
            #pragma unroll
            for (int j = 0; j < 4; ++j) {
                *(uint2*)&A_h[grow + j * 32][gseg * 4] = f4_to_h4(pa[j]);
                *(uint2*)&B_h[grow + j * 32][gseg * 4] = f4_to_h4(pb[j]);
            }
            __syncthreads();

            if (kt + 1 < K_TILES) {
                const int k0 = (kt + 1) * BK;
                #pragma unroll
                for (int j = 0; j < 4; ++j) {
                    pa[j] = *(const float4*)(x  + (size_t)(m0 + grow + j * 32) * UNITS + k0 + gseg * 4);
                    pb[j] = *(const float4*)(W1 + (size_t)(n0 + grow + j * 32) * UNITS + k0 + gseg * 4);
                }
            }

            #pragma unroll
            for (int ks = 0; ks < 2; ++ks) {       // two k16 steps per BK=32
                const uint32_t koff = ks * 32;     // 16 halves = 32 bytes
                uint32_t af[2][4];
                LDMX4(af[0][0], af[0][1], af[0][2], af[0][3], a_base + koff);
                LDMX4(af[1][0], af[1][1], af[1][2], af[1][3],
                      a_base + 16 * ROWB + koff);
                #pragma unroll
                for (int nfp = 0; nfp < 4; ++nfp) {
                    uint32_t bb[4];
                    LDMX4(bb[0], bb[1], bb[2], bb[3],
                          b_base + nfp * 16 * ROWB + koff);
                    mma_f16(d[0][nfp * 2 + 0], af[0], bb[0], bb[1]);
                    mma_f16(d[1][nfp * 2 + 0], af[1], bb[0], bb[1]);
                    mma_f16(d[0][nfp * 2 + 1], af[0], bb[2], bb[3]);
                    mma_f16(d[1][nfp * 2 + 1], af[1], bb[2], bb[3]);
                }
            }
        }

        // Epilogue: tanh + V-weighted reduce (c-frag layout == m16n8k8 case)
        #pragma unroll
        for (int mf = 0; mf < 2; ++mf) {
            #pragma unroll
            for (int nf = 0; nf < 8; ++nf) {
                const int n = n0 + wn * 64 + nf * 8 + 2 * thr;
                sacc[mf][0] += tanhf(d[mf][nf][0] + cs[n])     * vs[n];
                sacc[mf][0] += tanhf(d[mf][nf][1] + cs[n + 1]) * vs[n + 1];
                sacc[mf][1] += tanhf(d[mf][nf][2] + cs[n])     * vs[n];
                sacc[mf][1] += tanhf(d[mf][nf][3] + cs[n + 1]) * vs[n + 1];
            }
        }
    }

    // Reduce within quad (lanes sharing a row), then across the 2 wn warps
    #pragma unroll
    for (int mf = 0; mf < 2; ++mf) {
        #pragma unroll
        for (int h = 0; h < 2; ++h) {
            float v = sacc[mf][h];
            v += __shfl_xor_sync(0xffffffffu, v, 1);
            v += __shfl_xor_sync(0xffffffffu, v, 2);
            if (thr == 0)
                sred[wn][wm * 32 + mf * 16 + h * 8 + grp] = v;
        }
    }
    __syncthreads();
    if (tid < M_TILE)
        g_score[m0 + tid] = sred[0][tid] + sred[1][tid];
}

// ======================= Kernel C: softmax per batch =======================
__global__ void softmax_kernel(float* __restrict__ out_w) {
    __shared__ float s[NT];
    __shared__ float red[32];
    const int b = blockIdx.x;
    const int tid = threadIdx.x;
    const int lane = tid & 31, warp = tid >> 5;

    float lmax = -INFINITY;
    for (int t = tid; t < NT; t += 256) {
        const float v = g_score[b * NT + t];
        s[t] = v;
        lmax = fmaxf(lmax, v);
    }
    #pragma unroll
    for (int m = 16; m; m >>= 1)
        lmax = fmaxf(lmax, __shfl_xor_sync(0xffffffffu, lmax, m));
    if (lane == 0) red[warp] = lmax;
    __syncthreads();
    float bmax = red[0];
    #pragma unroll
    for (int w = 1; w < 8; w++) bmax = fmaxf(bmax, red[w]);

    float lsum = 0.f;
    for (int t = tid; t < NT; t += 256) {
        const float e = __expf(s[t] - bmax);
        s[t] = e;
        lsum += e;
    }
    #pragma unroll
    for (int m = 16; m; m >>= 1)
        lsum += __shfl_xor_sync(0xffffffffu, lsum, m);
    __syncthreads();
    if (lane == 0) red[warp] = lsum;
    __syncthreads();
    float bsum = 0.f;
    #pragma unroll
    for (int w = 0; w < 8; w++) bsum += red[w];
    const float inv = 1.f / bsum;
    for (int t = tid; t < NT; t += 256)
        out_w[b * NT + t] = s[t] * inv;
}

// ================= Kernel D: context partials (8-way t-split) ==============
__global__ void __launch_bounds__(256) context_part_kernel(
    const float* __restrict__ x, const float* __restrict__ w) {
    __shared__ float ws[NT / CTX_SPLIT];    // 256
    const int b  = blockIdx.x;
    const int uc = blockIdx.y;
    const int tc = blockIdx.z;
    const int t0 = tc * (NT / CTX_SPLIT);
    ws[threadIdx.x] = w[b * NT + t0 + threadIdx.x];
    __syncthreads();
    const int u = uc * 256 + threadIdx.x;
    const float* xp = x + (size_t)b * NT * UNITS + (size_t)t0 * UNITS + u;
    float a0 = 0.f, a1 = 0.f, a2 = 0.f, a3 = 0.f;
    for (int t = 0; t < NT / CTX_SPLIT; t += 4) {
        a0 += ws[t + 0] * xp[(size_t)(t + 0) * UNITS];
        a1 += ws[t + 1] * xp[(size_t)(t + 1) * UNITS];
        a2 += ws[t + 2] * xp[(size_t)(t + 2) * UNITS];
        a3 += ws[t + 3] * xp[(size_t)(t + 3) * UNITS];
    }
    g_ctxp[(size_t)tc * NB * UNITS + b * UNITS + u] = (a0 + a1) + (a2 + a3);
}

__global__ void context_reduce_kernel(float* __restrict__ out_ctx) {
    const int i = blockIdx.x * 256 + threadIdx.x;   // 0..32767
    float s = 0.f;
    #pragma unroll
    for (int p = 0; p < CTX_SPLIT; ++p)
        s += g_ctxp[(size_t)p * NB * UNITS + i];
    out_ctx[i] = s;
}

// ---------------------------------------------------------------------------
extern "C" void kernel_launch(void* const* d_in, const int* in_sizes, int n_in,
                              void* d_out, int out_size) {
    const float* x      = (const float*)d_in[0];
    const float* hidden = (const float*)d_in[1];
    const float* W1_w   = (const float*)d_in[2];
    const float* W1_b   = (const float*)d_in[3];
    const float* W2_w   = (const float*)d_in[4];
    const float* W2_b   = (const float*)d_in[5];
    const float* V_w    = (const float*)d_in[6];
    // d_in[7] = V_b: softmax-invariant, unused.

    float* out     = (float*)d_out;
    float* out_ctx = out;                   // 32*1024
    float* out_w   = out + NB * UNITS;      // 32*2048

    bias_hidden_kernel<<<dim3(NB, 8), 256>>>(hidden, W2_w, W1_b, W2_b);
    score_kernel<<<M_TOTAL / M_TILE, 256>>>(x, W1_w, V_w);
    softmax_kernel<<<NB, 256>>>(out_w);
    context_part_kernel<<<dim3(NB, 4, CTX_SPLIT), 256>>>(x, out_w);
    context_reduce_kernel<<<NB * UNITS / 256, 256>>>(out_ctx);
}

// round 6
// speedup vs baseline: 7.5521x; 1.5258x over previous
#include <cuda_runtime.h>
#include <cuda_fp16.h>
#include <math.h>
#include <stdint.h>

#define UNITS 1024
#define NB    32
#define NT    2048
#define M_TOTAL (NB * NT)

#define M_TILE 128
#define N_CHUNK 256
#define BK 32
#define N_CHUNKS (UNITS / N_CHUNK)   // 4
#define K_TILES  (UNITS / BK)        // 32
#define PADH 8
#define ROWH (BK + PADH)             // 40 halves
#define ROWB (ROWH * 2)              // 80 bytes

// dynamic smem byte offsets
#define S_A(buf)  ((buf) * 10240)                 // 128 x 80B each
#define S_B(buf)  (20480 + (buf) * 20480)         // 256 x 80B each
#define S_CS      61440
#define S_VS      65536
#define S_RED     69632                           // float[4][128]
#define S_TOTAL   71680

// ---- scratch (allocation-free rule: __device__ globals) ----
__device__ __half g_xh[(size_t)M_TOTAL * UNITS];  // x in fp16
__device__ __half g_w1h[UNITS * UNITS];           // W1 in fp16
__device__ float  g_c[NB * UNITS];
__device__ float  g_score[NB * NT];
#define CTX_SPLIT 8
__device__ float  g_ctxp[CTX_SPLIT * NB * UNITS];

__device__ __forceinline__ uint32_t sptr(const void* p) {
    return (uint32_t)__cvta_generic_to_shared(p);
}
#define LDMX4(r0, r1, r2, r3, a) \
    asm volatile("ldmatrix.sync.aligned.m8n8.x4.shared.b16 {%0,%1,%2,%3}, [%4];" \
                 : "=r"(r0), "=r"(r1), "=r"(r2), "=r"(r3) : "r"(a))

__device__ __forceinline__ void mma_f16(float d[4], const uint32_t a[4],
                                        const uint32_t b0, const uint32_t b1) {
    asm volatile(
        "mma.sync.aligned.m16n8k16.row.col.f32.f16.f16.f32 "
        "{%0,%1,%2,%3}, {%4,%5,%6,%7}, {%8,%9}, {%0,%1,%2,%3};"
        : "+f"(d[0]), "+f"(d[1]), "+f"(d[2]), "+f"(d[3])
        : "r"(a[0]), "r"(a[1]), "r"(a[2]), "r"(a[3]), "r"(b0), "r"(b1));
}

// ==================== converters: fp32 -> fp16 (one-off) ====================
__device__ __forceinline__ uint2 pack4(float4 v) {
    __half2 lo = __floats2half2_rn(v.x, v.y);
    __half2 hi = __floats2half2_rn(v.z, v.w);
    uint2 r;
    r.x = *(uint32_t*)&lo;
    r.y = *(uint32_t*)&hi;
    return r;
}
__global__ void convert_x_kernel(const float* __restrict__ x) {
    const size_t i = ((size_t)blockIdx.x * 256 + threadIdx.x) * 8;
    const float4 v0 = *(const float4*)(x + i);
    const float4 v1 = *(const float4*)(x + i + 4);
    uint2 a = pack4(v0), b = pack4(v1);
    *(uint4*)(g_xh + i) = make_uint4(a.x, a.y, b.x, b.y);
}
__global__ void convert_w1_kernel(const float* __restrict__ w) {
    const size_t i = ((size_t)blockIdx.x * 256 + threadIdx.x) * 8;
    const float4 v0 = *(const float4*)(w + i);
    const float4 v1 = *(const float4*)(w + i + 4);
    uint2 a = pack4(v0), b = pack4(v1);
    *(uint4*)(g_w1h + i) = make_uint4(a.x, a.y, b.x, b.y);
}

// ============================ Kernel A: c[b][v] ============================
__global__ void bias_hidden_kernel(const float* __restrict__ hidden,
                                   const float* __restrict__ W2_w,
                                   const float* __restrict__ W1_b,
                                   const float* __restrict__ W2_b) {
    __shared__ float hs[UNITS];
    const int b = blockIdx.x;
    for (int u = threadIdx.x; u < UNITS; u += 256)
        hs[u] = hidden[b * UNITS + u];
    __syncthreads();
    const int warp = threadIdx.x >> 5, lane = threadIdx.x & 31;
    const int v0 = blockIdx.y * 128;
    for (int v = v0 + warp; v < v0 + 128; v += 8) {
        const float* wr = W2_w + (size_t)v * UNITS;
        float s = 0.f;
        #pragma unroll 8
        for (int u = lane; u < UNITS; u += 32) s += hs[u] * wr[u];
        #pragma unroll
        for (int m = 16; m; m >>= 1) s += __shfl_xor_sync(0xffffffffu, s, m);
        if (lane == 0) g_c[b * UNITS + v] = s + W1_b[v] + W2_b[v];
    }
}

// ====== Kernel B: fp16 mma m16n8k16, double-buffered, fused tanh/V =========
// 512 threads = 16 warps (4m x 4n). CTA tile 128 x 256 per chunk, 4 chunks.
__global__ void __launch_bounds__(512, 1) score_kernel(
    const float* __restrict__ Vw) {
    extern __shared__ char smem[];
    const uint32_t sb = sptr(smem);

    const int tid  = threadIdx.x;
    const int wid  = tid >> 5, lane = tid & 31;
    const int wm   = wid >> 2;          // 0..3  rows wm*32
    const int wn   = wid & 3;           // 0..3  cols wn*64
    const int grp  = lane >> 2;
    const int thr  = lane & 3;
    const int m0   = blockIdx.x * M_TILE;
    const int b    = m0 / NT;

    float* cs = (float*)(smem + S_CS);
    float* vs = (float*)(smem + S_VS);
    for (int i = tid; i < UNITS; i += 512) {
        cs[i] = g_c[b * UNITS + i];
        vs[i] = Vw[i];
    }

    // global load mapping: per thread one uint4 (8 halves) of A,
    // two uint4 of B (rows arow, arow+128)
    const int arow = tid >> 2;          // 0..127
    const int aseg = tid & 3;           // uint4 seg within 32-half slab
    const uint4* xg = (const uint4*)(g_xh + (size_t)(m0 + arow) * UNITS);

    // ldmatrix fragment bases
    const uint32_t aF = sb + (uint32_t)((wm * 32 + (lane & 15)) * ROWB
                                        + (lane >> 4) * 16);
    const uint32_t bF = sb + 20480u
        + (uint32_t)((wn * 64 + ((lane >> 4) << 3) + (lane & 7)) * ROWB
                     + ((lane >> 3) & 1) * 16);

    float sacc[2][2] = {{0.f, 0.f}, {0.f, 0.f}};

    for (int nc = 0; nc < N_CHUNKS; ++nc) {
        const int n0 = nc * N_CHUNK;
        const uint4* w1g0 = (const uint4*)(g_w1h + (size_t)(n0 + arow) * UNITS);
        const uint4* w1g1 = (const uint4*)(g_w1h + (size_t)(n0 + arow + 128) * UNITS);

        float d[2][8][4];
        #pragma unroll
        for (int mf = 0; mf < 2; ++mf)
            #pragma unroll
            for (int nf = 0; nf < 8; ++nf)
                #pragma unroll
                for (int q = 0; q < 4; ++q) d[mf][nf][q] = 0.f;

        // preload k-tile 0 into buffer 0
        {
            const uint4 va  = xg[aseg];
            const uint4 vb0 = w1g0[aseg];
            const uint4 vb1 = w1g1[aseg];
            *(uint4*)(smem + S_A(0) + arow * ROWB + aseg * 16) = va;
            *(uint4*)(smem + S_B(0) + arow * ROWB + aseg * 16) = vb0;
            *(uint4*)(smem + S_B(0) + (arow + 128) * ROWB + aseg * 16) = vb1;
        }
        __syncthreads();

        for (int kt = 0; kt < K_TILES; ++kt) {
            const int cur = kt & 1;
            uint4 va, vb0, vb1;
            if (kt + 1 < K_TILES) {
                const int q = (kt + 1) * 4 + aseg;
                va  = xg[q];
                vb0 = w1g0[q];
                vb1 = w1g1[q];
            }

            const uint32_t abuf = aF + (uint32_t)(cur * 10240);
            const uint32_t bbuf = bF + (uint32_t)(cur * 20480);
            #pragma unroll
            for (int ks = 0; ks < 2; ++ks) {
                const uint32_t koff = ks * 32;
                uint32_t af[2][4];
                LDMX4(af[0][0], af[0][1], af[0][2], af[0][3], abuf + koff);
                LDMX4(af[1][0], af[1][1], af[1][2], af[1][3],
                      abuf + 16 * ROWB + koff);
                #pragma unroll
                for (int nfp = 0; nfp < 4; ++nfp) {
                    uint32_t bb[4];
                    LDMX4(bb[0], bb[1], bb[2], bb[3],
                          bbuf + nfp * 16 * ROWB + koff);
                    mma_f16(d[0][nfp * 2 + 0], af[0], bb[0], bb[1]);
                    mma_f16(d[1][nfp * 2 + 0], af[1], bb[0], bb[1]);
                    mma_f16(d[0][nfp * 2 + 1], af[0], bb[2], bb[3]);
                    mma_f16(d[1][nfp * 2 + 1], af[1], bb[2], bb[3]);
                }
            }

            if (kt + 1 < K_TILES) {
                const int nxt = cur ^ 1;
                *(uint4*)(smem + S_A(nxt) + arow * ROWB + aseg * 16) = va;
                *(uint4*)(smem + S_B(nxt) + arow * ROWB + aseg * 16) = vb0;
                *(uint4*)(smem + S_B(nxt) + (arow + 128) * ROWB + aseg * 16) = vb1;
            }
            __syncthreads();
        }

        // Epilogue: tanh + V-weighted reduce
        #pragma unroll
        for (int mf = 0; mf < 2; ++mf) {
            #pragma unroll
            for (int nf = 0; nf < 8; ++nf) {
                const int n = n0 + wn * 64 + nf * 8 + 2 * thr;
                sacc[mf][0] += tanhf(d[mf][nf][0] + cs[n])     * vs[n];
                sacc[mf][0] += tanhf(d[mf][nf][1] + cs[n + 1]) * vs[n + 1];
                sacc[mf][1] += tanhf(d[mf][nf][2] + cs[n])     * vs[n];
                sacc[mf][1] += tanhf(d[mf][nf][3] + cs[n + 1]) * vs[n + 1];
            }
        }
    }

    // quad reduce, then across the 4 wn warps via smem
    float (*sred)[M_TILE] = (float(*)[M_TILE])(smem + S_RED);
    #pragma unroll
    for (int mf = 0; mf < 2; ++mf) {
        #pragma unroll
        for (int h = 0; h < 2; ++h) {
            float v = sacc[mf][h];
            v += __shfl_xor_sync(0xffffffffu, v, 1);
            v += __shfl_xor_sync(0xffffffffu, v, 2);
            if (thr == 0)
                sred[wn][wm * 32 + mf * 16 + h * 8 + grp] = v;
        }
    }
    __syncthreads();
    if (tid < M_TILE)
        g_score[m0 + tid] = (sred[0][tid] + sred[1][tid])
                          + (sred[2][tid] + sred[3][tid]);
}

// ======================= Kernel C: softmax per batch =======================
__global__ void softmax_kernel(float* __restrict__ out_w) {
    __shared__ float s[NT];
    __shared__ float red[32];
    const int b = blockIdx.x;
    const int tid = threadIdx.x;
    const int lane = tid & 31, warp = tid >> 5;

    float lmax = -INFINITY;
    for (int t = tid; t < NT; t += 256) {
        const float v = g_score[b * NT + t];
        s[t] = v;
        lmax = fmaxf(lmax, v);
    }
    #pragma unroll
    for (int m = 16; m; m >>= 1)
        lmax = fmaxf(lmax, __shfl_xor_sync(0xffffffffu, lmax, m));
    if (lane == 0) red[warp] = lmax;
    __syncthreads();
    float bmax = red[0];
    #pragma unroll
    for (int w = 1; w < 8; w++) bmax = fmaxf(bmax, red[w]);

    float lsum = 0.f;
    for (int t = tid; t < NT; t += 256) {
        const float e = __expf(s[t] - bmax);
        s[t] = e;
        lsum += e;
    }
    #pragma unroll
    for (int m = 16; m; m >>= 1)
        lsum += __shfl_xor_sync(0xffffffffu, lsum, m);
    __syncthreads();
    if (lane == 0) red[warp] = lsum;
    __syncthreads();
    float bsum = 0.f;
    #pragma unroll
    for (int w = 0; w < 8; w++) bsum += red[w];
    const float inv = 1.f / bsum;
    for (int t = tid; t < NT; t += 256)
        out_w[b * NT + t] = s[t] * inv;
}

// ====== Kernel D: context partials (8-way t-split, fp16 x) =================
__global__ void __launch_bounds__(256) context_part_kernel(
    const float* __restrict__ w) {
    __shared__ float ws[NT / CTX_SPLIT];    // 256
    const int b  = blockIdx.x;
    const int uc = blockIdx.y;
    const int tc = blockIdx.z;
    const int t0 = tc * (NT / CTX_SPLIT);
    ws[threadIdx.x] = w[b * NT + t0 + threadIdx.x];
    __syncthreads();
    const int u = uc * 256 + threadIdx.x;
    const __half* xp = g_xh + (size_t)b * NT * UNITS + (size_t)t0 * UNITS + u;
    float a0 = 0.f, a1 = 0.f, a2 = 0.f, a3 = 0.f;
    for (int t = 0; t < NT / CTX_SPLIT; t += 4) {
        a0 += ws[t + 0] * __half2float(xp[(size_t)(t + 0) * UNITS]);
        a1 += ws[t + 1] * __half2float(xp[(size_t)(t + 1) * UNITS]);
        a2 += ws[t + 2] * __half2float(xp[(size_t)(t + 2) * UNITS]);
        a3 += ws[t + 3] * __half2float(xp[(size_t)(t + 3) * UNITS]);
    }
    g_ctxp[(size_t)tc * NB * UNITS + b * UNITS + u] = (a0 + a1) + (a2 + a3);
}

__global__ void context_reduce_kernel(float* __restrict__ out_ctx) {
    const int i = blockIdx.x * 256 + threadIdx.x;
    float s = 0.f;
    #pragma unroll
    for (int p = 0; p < CTX_SPLIT; ++p)
        s += g_ctxp[(size_t)p * NB * UNITS + i];
    out_ctx[i] = s;
}

// ---------------------------------------------------------------------------
extern "C" void kernel_launch(void* const* d_in, const int* in_sizes, int n_in,
                              void* d_out, int out_size) {
    const float* x      = (const float*)d_in[0];
    const float* hidden = (const float*)d_in[1];
    const float* W1_w   = (const float*)d_in[2];
    const float* W1_b   = (const float*)d_in[3];
    const float* W2_w   = (const float*)d_in[4];
    const float* W2_b   = (const float*)d_in[5];
    const float* V_w    = (const float*)d_in[6];
    // d_in[7] = V_b: softmax-invariant, unused.

    float* out     = (float*)d_out;
    float* out_ctx = out;                   // 32*1024
    float* out_w   = out + NB * UNITS;      // 32*2048

    cudaFuncSetAttribute(score_kernel,
                         cudaFuncAttributeMaxDynamicSharedMemorySize, S_TOTAL);

    convert_x_kernel<<<(int)((size_t)M_TOTAL * UNITS / (256 * 8)), 256>>>(x);
    convert_w1_kernel<<<UNITS * UNITS / (256 * 8), 256>>>(W1_w);
    bias_hidden_kernel<<<dim3(NB, 8), 256>>>(hidden, W2_w, W1_b, W2_b);
    score_kernel<<<M_TOTAL / M_TILE, 512, S_TOTAL>>>(V_w);
    softmax_kernel<<<NB, 256>>>(out_w);
    context_part_kernel<<<dim3(NB, 4, CTX_SPLIT), 256>>>(out_w);
    context_reduce_kernel<<<NB * UNITS / 256, 256>>>(out_ctx);
}

// round 7
// speedup vs baseline: 8.1069x; 1.0735x over previous
#include <cuda_runtime.h>
#include <cuda_fp16.h>
#include <math.h>
#include <stdint.h>

#define UNITS 1024
#define NB    32
#define NT    2048
#define M_TOTAL (NB * NT)

#define M_TILE 128
#define N_CHUNK 256
#define BK 32
#define N_CHUNKS (UNITS / N_CHUNK)   // 4
#define K_TILES  (UNITS / BK)        // 32
#define PADH 8
#define ROWH (BK + PADH)             // 40 halves
#define ROWB (ROWH * 2)              // 80 bytes

// dynamic smem byte offsets
#define S_A(buf)  ((buf) * 10240)                 // 128 x 80B each
#define S_B(buf)  (20480 + (buf) * 20480)         // 256 x 80B each
#define S_CS      61440
#define S_VS      65536
#define S_RED     69632                           // float[4][128]
#define S_TOTAL   71680

// ---- scratch (allocation-free rule: __device__ globals) ----
__device__ __half g_xh[(size_t)M_TOTAL * UNITS];  // x in fp16
__device__ __half g_w1h[UNITS * UNITS];           // W1 in fp16
__device__ float  g_c[NB * UNITS];
__device__ float  g_score[NB * NT];
#define CTX_SPLIT 8
__device__ float  g_ctxp[CTX_SPLIT * NB * UNITS];

__device__ __forceinline__ uint32_t sptr(const void* p) {
    return (uint32_t)__cvta_generic_to_shared(p);
}
#define LDMX4(r0, r1, r2, r3, a) \
    asm volatile("ldmatrix.sync.aligned.m8n8.x4.shared.b16 {%0,%1,%2,%3}, [%4];" \
                 : "=r"(r0), "=r"(r1), "=r"(r2), "=r"(r3) : "r"(a))

__device__ __forceinline__ void mma_f16(float d[4], const uint32_t a[4],
                                        const uint32_t b0, const uint32_t b1) {
    asm volatile(
        "mma.sync.aligned.m16n8k16.row.col.f32.f16.f16.f32 "
        "{%0,%1,%2,%3}, {%4,%5,%6,%7}, {%8,%9}, {%0,%1,%2,%3};"
        : "+f"(d[0]), "+f"(d[1]), "+f"(d[2]), "+f"(d[3])
        : "r"(a[0]), "r"(a[1]), "r"(a[2]), "r"(a[3]), "r"(b0), "r"(b1));
}

// ==================== converters: fp32 -> fp16 (one-off) ====================
__device__ __forceinline__ uint2 pack4(float4 v) {
    __half2 lo = __floats2half2_rn(v.x, v.y);
    __half2 hi = __floats2half2_rn(v.z, v.w);
    uint2 r;
    r.x = *(uint32_t*)&lo;
    r.y = *(uint32_t*)&hi;
    return r;
}
__global__ void convert_x_kernel(const float* __restrict__ x) {
    const size_t i = ((size_t)blockIdx.x * 256 + threadIdx.x) * 8;
    const float4 v0 = *(const float4*)(x + i);
    const float4 v1 = *(const float4*)(x + i + 4);
    uint2 a = pack4(v0), b = pack4(v1);
    *(uint4*)(g_xh + i) = make_uint4(a.x, a.y, b.x, b.y);
}
__global__ void convert_w1_kernel(const float* __restrict__ w) {
    const size_t i = ((size_t)blockIdx.x * 256 + threadIdx.x) * 8;
    const float4 v0 = *(const float4*)(w + i);
    const float4 v1 = *(const float4*)(w + i + 4);
    uint2 a = pack4(v0), b = pack4(v1);
    *(uint4*)(g_w1h + i) = make_uint4(a.x, a.y, b.x, b.y);
}

// ============================ Kernel A: c[b][v] ============================
__global__ void bias_hidden_kernel(const float* __restrict__ hidden,
                                   const float* __restrict__ W2_w,
                                   const float* __restrict__ W1_b,
                                   const float* __restrict__ W2_b) {
    __shared__ float hs[UNITS];
    const int b = blockIdx.x;
    for (int u = threadIdx.x; u < UNITS; u += 256)
        hs[u] = hidden[b * UNITS + u];
    __syncthreads();
    const int warp = threadIdx.x >> 5, lane = threadIdx.x & 31;
    const int v0 = blockIdx.y * 128;
    for (int v = v0 + warp; v < v0 + 128; v += 8) {
        const float* wr = W2_w + (size_t)v * UNITS;
        float s = 0.f;
        #pragma unroll 8
        for (int u = lane; u < UNITS; u += 32) s += hs[u] * wr[u];
        #pragma unroll
        for (int m = 16; m; m >>= 1) s += __shfl_xor_sync(0xffffffffu, s, m);
        if (lane == 0) g_c[b * UNITS + v] = s + W1_b[v] + W2_b[v];
    }
}

// ====== Kernel B: fp16 mma m16n8k16, 64x64 warp tile, fused tanh/V =========
// 256 threads = 8 warps (2m x 4n). CTA tile 128 x 256 per chunk, 4 chunks.
// ldmatrix-per-MMA = 0.25 (halved vs 32x64 warp tile).
__global__ void __launch_bounds__(256, 1) score_kernel(
    const float* __restrict__ Vw) {
    extern __shared__ char smem[];
    const uint32_t sb = sptr(smem);

    const int tid  = threadIdx.x;
    const int wid  = tid >> 5, lane = tid & 31;
    const int wm   = wid >> 2;          // 0..1  rows wm*64
    const int wn   = wid & 3;           // 0..3  cols wn*64
    const int grp  = lane >> 2;
    const int thr  = lane & 3;
    const int m0   = blockIdx.x * M_TILE;
    const int b    = m0 / NT;

    float* cs = (float*)(smem + S_CS);
    float* vs = (float*)(smem + S_VS);
    for (int i = tid; i < UNITS; i += 256) {
        cs[i] = g_c[b * UNITS + i];
        vs[i] = Vw[i];
    }

    // global load mapping: A 512 uint4/ktile -> 2/thread; B 1024 -> 4/thread
    const int ar0 = tid >> 2;                 // A row for j=0 (0..63)
    const int ar1 = ((tid + 256) >> 2);       // A row for j=1 (64..127)
    const int seg = tid & 3;
    const uint4* xg0 = (const uint4*)(g_xh + (size_t)(m0 + ar0) * UNITS);
    const uint4* xg1 = (const uint4*)(g_xh + (size_t)(m0 + ar1) * UNITS);

    // ldmatrix fragment bases
    const uint32_t aF = sb + (uint32_t)((wm * 64 + (lane & 15)) * ROWB
                                        + (lane >> 4) * 16);
    const uint32_t bF = sb + 20480u
        + (uint32_t)((wn * 64 + ((lane >> 4) << 3) + (lane & 7)) * ROWB
                     + ((lane >> 3) & 1) * 16);

    float sacc[4][2];
    #pragma unroll
    for (int mf = 0; mf < 4; ++mf) { sacc[mf][0] = 0.f; sacc[mf][1] = 0.f; }

    for (int nc = 0; nc < N_CHUNKS; ++nc) {
        const int n0 = nc * N_CHUNK;
        const uint4* wg[4];
        #pragma unroll
        for (int j = 0; j < 4; ++j)
            wg[j] = (const uint4*)(g_w1h + (size_t)(n0 + ((tid + j * 256) >> 2)) * UNITS);

        float d[4][8][4];
        #pragma unroll
        for (int mf = 0; mf < 4; ++mf)
            #pragma unroll
            for (int nf = 0; nf < 8; ++nf)
                #pragma unroll
                for (int q = 0; q < 4; ++q) d[mf][nf][q] = 0.f;

        // preload k-tile 0 into buffer 0
        {
            *(uint4*)(smem + S_A(0) + ar0 * ROWB + seg * 16) = xg0[seg];
            *(uint4*)(smem + S_A(0) + ar1 * ROWB + seg * 16) = xg1[seg];
            #pragma unroll
            for (int j = 0; j < 4; ++j) {
                const int brow = (tid + j * 256) >> 2;
                *(uint4*)(smem + S_B(0) + brow * ROWB + seg * 16) = wg[j][seg];
            }
        }
        __syncthreads();

        for (int kt = 0; kt < K_TILES; ++kt) {
            const int cur = kt & 1;
            uint4 va0, va1, vb[4];
            if (kt + 1 < K_TILES) {
                const int q = (kt + 1) * 4 + seg;
                va0 = xg0[q];
                va1 = xg1[q];
                #pragma unroll
                for (int j = 0; j < 4; ++j) vb[j] = wg[j][q];
            }

            const uint32_t abuf = aF + (uint32_t)(cur * 10240);
            const uint32_t bbuf = bF + (uint32_t)(cur * 20480);
            #pragma unroll
            for (int ks = 0; ks < 2; ++ks) {
                const uint32_t koff = ks * 32;
                uint32_t af[4][4];
                #pragma unroll
                for (int mf = 0; mf < 4; ++mf)
                    LDMX4(af[mf][0], af[mf][1], af[mf][2], af[mf][3],
                          abuf + mf * 16 * ROWB + koff);
                #pragma unroll
                for (int nfp = 0; nfp < 4; ++nfp) {
                    uint32_t bb[4];
                    LDMX4(bb[0], bb[1], bb[2], bb[3],
                          bbuf + nfp * 16 * ROWB + koff);
                    #pragma unroll
                    for (int mf = 0; mf < 4; ++mf) {
                        mma_f16(d[mf][nfp * 2 + 0], af[mf], bb[0], bb[1]);
                        mma_f16(d[mf][nfp * 2 + 1], af[mf], bb[2], bb[3]);
                    }
                }
            }

            if (kt + 1 < K_TILES) {
                const int nxt = cur ^ 1;
                *(uint4*)(smem + S_A(nxt) + ar0 * ROWB + seg * 16) = va0;
                *(uint4*)(smem + S_A(nxt) + ar1 * ROWB + seg * 16) = va1;
                #pragma unroll
                for (int j = 0; j < 4; ++j) {
                    const int brow = (tid + j * 256) >> 2;
                    *(uint4*)(smem + S_B(nxt) + brow * ROWB + seg * 16) = vb[j];
                }
            }
            __syncthreads();
        }

        // Epilogue: tanh + V-weighted reduce
        #pragma unroll
        for (int mf = 0; mf < 4; ++mf) {
            #pragma unroll
            for (int nf = 0; nf < 8; ++nf) {
                const int n = n0 + wn * 64 + nf * 8 + 2 * thr;
                sacc[mf][0] += tanhf(d[mf][nf][0] + cs[n])     * vs[n];
                sacc[mf][0] += tanhf(d[mf][nf][1] + cs[n + 1]) * vs[n + 1];
                sacc[mf][1] += tanhf(d[mf][nf][2] + cs[n])     * vs[n];
                sacc[mf][1] += tanhf(d[mf][nf][3] + cs[n + 1]) * vs[n + 1];
            }
        }
    }

    // quad reduce, then across the 4 wn warps via smem
    float (*sred)[M_TILE] = (float(*)[M_TILE])(smem + S_RED);
    #pragma unroll
    for (int mf = 0; mf < 4; ++mf) {
        #pragma unroll
        for (int h = 0; h < 2; ++h) {
            float v = sacc[mf][h];
            v += __shfl_xor_sync(0xffffffffu, v, 1);
            v += __shfl_xor_sync(0xffffffffu, v, 2);
            if (thr == 0)
                sred[wn][wm * 64 + mf * 16 + h * 8 + grp] = v;
        }
    }
    __syncthreads();
    if (tid < M_TILE)
        g_score[m0 + tid] = (sred[0][tid] + sred[1][tid])
                          + (sred[2][tid] + sred[3][tid]);
}

// ======================= Kernel C: softmax per batch =======================
__global__ void softmax_kernel(float* __restrict__ out_w) {
    __shared__ float s[NT];
    __shared__ float red[32];
    const int b = blockIdx.x;
    const int tid = threadIdx.x;
    const int lane = tid & 31, warp = tid >> 5;

    float lmax = -INFINITY;
    for (int t = tid; t < NT; t += 256) {
        const float v = g_score[b * NT + t];
        s[t] = v;
        lmax = fmaxf(lmax, v);
    }
    #pragma unroll
    for (int m = 16; m; m >>= 1)
        lmax = fmaxf(lmax, __shfl_xor_sync(0xffffffffu, lmax, m));
    if (lane == 0) red[warp] = lmax;
    __syncthreads();
    float bmax = red[0];
    #pragma unroll
    for (int w = 1; w < 8; w++) bmax = fmaxf(bmax, red[w]);

    float lsum = 0.f;
    for (int t = tid; t < NT; t += 256) {
        const float e = __expf(s[t] - bmax);
        s[t] = e;
        lsum += e;
    }
    #pragma unroll
    for (int m = 16; m; m >>= 1)
        lsum += __shfl_xor_sync(0xffffffffu, lsum, m);
    __syncthreads();
    if (lane == 0) red[warp] = lsum;
    __syncthreads();
    float bsum = 0.f;
    #pragma unroll
    for (int w = 0; w < 8; w++) bsum += red[w];
    const float inv = 1.f / bsum;
    for (int t = tid; t < NT; t += 256)
        out_w[b * NT + t] = s[t] * inv;
}

// ====== Kernel D: context partials (8-way t-split, fp16 x) =================
__global__ void __launch_bounds__(256) context_part_kernel(
    const float* __restrict__ w) {
    __shared__ float ws[NT / CTX_SPLIT];    // 256
    const int b  = blockIdx.x;
    const int uc = blockIdx.y;
    const int tc = blockIdx.z;
    const int t0 = tc * (NT / CTX_SPLIT);
    ws[threadIdx.x] = w[b * NT + t0 + threadIdx.x];
    __syncthreads();
    const int u = uc * 256 + threadIdx.x;
    const __half* xp = g_xh + (size_t)b * NT * UNITS + (size_t)t0 * UNITS + u;
    float a0 = 0.f, a1 = 0.f, a2 = 0.f, a3 = 0.f;
    for (int t = 0; t < NT / CTX_SPLIT; t += 4) {
        a0 += ws[t + 0] * __half2float(xp[(size_t)(t + 0) * UNITS]);
        a1 += ws[t + 1] * __half2float(xp[(size_t)(t + 1) * UNITS]);
        a2 += ws[t + 2] * __half2float(xp[(size_t)(t + 2) * UNITS]);
        a3 += ws[t + 3] * __half2float(xp[(size_t)(t + 3) * UNITS]);
    }
    g_ctxp[(size_t)tc * NB * UNITS + b * UNITS + u] = (a0 + a1) + (a2 + a3);
}

__global__ void context_reduce_kernel(float* __restrict__ out_ctx) {
    const int i = blockIdx.x * 256 + threadIdx.x;
    float s = 0.f;
    #pragma unroll
    for (int p = 0; p < CTX_SPLIT; ++p)
        s += g_ctxp[(size_t)p * NB * UNITS + i];
    out_ctx[i] = s;
}

// ---------------------------------------------------------------------------
extern "C" void kernel_launch(void* const* d_in, const int* in_sizes, int n_in,
                              void* d_out, int out_size) {
    const float* x      = (const float*)d_in[0];
    const float* hidden = (const float*)d_in[1];
    const float* W1_w   = (const float*)d_in[2];
    const float* W1_b   = (const float*)d_in[3];
    const float* W2_w   = (const float*)d_in[4];
    const float* W2_b   = (const float*)d_in[5];
    const float* V_w    = (const float*)d_in[6];
    // d_in[7] = V_b: softmax-invariant, unused.

    float* out     = (float*)d_out;
    float* out_ctx = out;                   // 32*1024
    float* out_w   = out + NB * UNITS;      // 32*2048

    cudaFuncSetAttribute(score_kernel,
                         cudaFuncAttributeMaxDynamicSharedMemorySize, S_TOTAL);

    convert_x_kernel<<<(int)((size_t)M_TOTAL * UNITS / (256 * 8)), 256>>>(x);
    convert_w1_kernel<<<UNITS * UNITS / (256 * 8), 256>>>(W1_w);
    bias_hidden_kernel<<<dim3(NB, 8), 256>>>(hidden, W2_w, W1_b, W2_b);
    score_kernel<<<M_TOTAL / M_TILE, 256, S_TOTAL>>>(V_w);
    softmax_kernel<<<NB, 256>>>(out_w);
    context_part_kernel<<<dim3(NB, 4, CTX_SPLIT), 256>>>(out_w);
    context_reduce_kernel<<<NB * UNITS / 256, 256>>>(out_ctx);
}